// round 2
// baseline (speedup 1.0000x reference)
#include <cuda_runtime.h>
#include <math.h>

// ---------------- problem constants ----------------
#define TOTN   131072      // B*N nodes
#define EMAX   1048576
#define FDIM   64
#define HSD    128
#define RSD    32
#define NPG    4096        // nodes per graph (temporal length)

// ---------------- device scratch (no cudaMalloc allowed) ----------------
__device__ int   g_is64;
__device__ float g_dinv [TOTN];
__device__ int   g_cnt  [TOTN];
__device__ int   g_rowp [TOTN + 1];
__device__ int   g_curs [TOTN];
__device__ int   g_adj  [EMAX];
__device__ float g_A1   [TOTN * FDIM];        // layer1 aggregated input
__device__ float g_H1   [TOTN * HSD];         // after GCN1
__device__ float g_H2raw[TOTN * RSD];         // H1 @ W2
__device__ float g_H2   [TOTN * RSD];         // after GCN2
__device__ float g_A3   [TOTN * RSD];         // aggregated input of GCN3
__device__ float g_H3   [TOTN * HSD];         // after GCN3
__device__ float g_C1   [TOTN * HSD];
__device__ float g_C2   [TOTN * RSD];
__device__ float g_C3   [TOTN * HSD];

// ---------------- edge dtype detection ----------------
// edge values < 2^31, so if stored int64 every high word is 0.
__global__ void detect_kernel(const unsigned int* e) {
    if (blockIdx.x == 0 && threadIdx.x == 0) {
        int ok = 1;
        #pragma unroll 1
        for (int i = 0; i < 64; i++)
            if (e[2 * i + 1] != 0u) { ok = 0; break; }
        g_is64 = ok;
    }
}

__device__ __forceinline__ int edge_at(const void* e, int idx, int is64) {
    if (is64) return (int)((const long long*)e)[idx];
    return ((const int*)e)[idx];
}

// ---------------- CSR build ----------------
__global__ void zero_cnt_kernel(int* cnt, int n) {
    int i  = blockIdx.x * blockDim.x + threadIdx.x;
    int st = gridDim.x * blockDim.x;
    for (; i < n; i += st) cnt[i] = 0;
}

__global__ void count_kernel(const void* edges, int* cnt, int E) {
    int is64 = g_is64;
    int i  = blockIdx.x * blockDim.x + threadIdx.x;
    int st = gridDim.x * blockDim.x;
    for (; i < E; i += st) {
        int d = edge_at(edges, E + i, is64);
        atomicAdd(&cnt[d], 1);
    }
}

__global__ void dinv_kernel(const int* __restrict__ cnt, float* dinv, int n) {
    int i  = blockIdx.x * blockDim.x + threadIdx.x;
    int st = gridDim.x * blockDim.x;
    for (; i < n; i += st) dinv[i] = rsqrtf((float)cnt[i] + 1.0f);
}

// single-block scan over TOTN counts -> row_ptr (exclusive) and cursor copy
__global__ void __launch_bounds__(1024)
scan_kernel(const int* __restrict__ cnt, int* row_ptr, int* cursor) {
    const int T = 1024;
    const int C = TOTN / T;    // 128
    int tid  = threadIdx.x;
    int base = tid * C;
    int s = 0;
    #pragma unroll 8
    for (int c = 0; c < C; c++) s += cnt[base + c];
    __shared__ int sh[T];
    sh[tid] = s;
    __syncthreads();
    for (int off = 1; off < T; off <<= 1) {
        int v = (tid >= off) ? sh[tid - off] : 0;
        __syncthreads();
        sh[tid] += v;
        __syncthreads();
    }
    int run = sh[tid] - s;   // exclusive prefix of this chunk
    #pragma unroll 8
    for (int c = 0; c < C; c++) {
        row_ptr[base + c] = run;
        cursor[base + c]  = run;
        run += cnt[base + c];
    }
    if (tid == T - 1) row_ptr[TOTN] = run;
}

__global__ void fill_kernel(const void* edges, int* cursor, int* adj, int E) {
    int is64 = g_is64;
    int i  = blockIdx.x * blockDim.x + threadIdx.x;
    int st = gridDim.x * blockDim.x;
    for (; i < E; i += st) {
        int s = edge_at(edges, i, is64);
        int d = edge_at(edges, E + i, is64);
        int pos = atomicAdd(&cursor[d], 1);
        adj[pos] = s;
    }
}

// ---------------- CSR gather + fused epilogue ----------------
// OUT[d] = di^2 * ( sum_{s in N(d)} dinv[s]*X[s]  +  X[d] )   (+bias, relu)
// (identical arithmetic to the previous scatter+finish pipeline)
template <int D, int BIASRELU>
__global__ void gather_kernel(const int* __restrict__ row_ptr, const int* __restrict__ adj,
                              const float* __restrict__ dinv, const float* __restrict__ X,
                              const float* __restrict__ bias, float* __restrict__ OUT, int n) {
    int lane = threadIdx.x & 31;
    int node = (blockIdx.x * blockDim.x + threadIdx.x) >> 5;
    if (node >= n) return;
    int beg = row_ptr[node];
    int end = row_ptr[node + 1];
    float di = dinv[node];
    float c  = di * di;
    if (D == 64) {
        float ax = 0.0f, ay = 0.0f;
        for (int j = beg; j < end; j++) {
            int s = adj[j];
            float ws = __ldg(&dinv[s]);
            float2 v = ((const float2*)(X + (size_t)s * 64))[lane];
            ax = fmaf(ws, v.x, ax);
            ay = fmaf(ws, v.y, ay);
        }
        float2 xv = ((const float2*)(X + (size_t)node * 64))[lane];
        float2 o;
        o.x = c * (ax + xv.x);
        o.y = c * (ay + xv.y);
        if (BIASRELU) {
            o.x = fmaxf(o.x + bias[2 * lane],     0.0f);
            o.y = fmaxf(o.y + bias[2 * lane + 1], 0.0f);
        }
        ((float2*)(OUT + (size_t)node * 64))[lane] = o;
    } else {
        float acc = 0.0f;
        for (int j = beg; j < end; j++) {
            int s = adj[j];
            float ws = __ldg(&dinv[s]);
            acc = fmaf(ws, X[(size_t)s * 32 + lane], acc);
        }
        float v = c * (acc + X[(size_t)node * 32 + lane]);
        if (BIASRELU) v = fmaxf(v + bias[lane], 0.0f);
        OUT[(size_t)node * 32 + lane] = v;
    }
}

// ---------------- tiled fp32 GEMM: C[M,BN] = A[M,K] @ B[K,BN] (+bias)(+relu) ----------------
template <int BM, int BN, int BK, int TM, int TN>
__global__ void __launch_bounds__((BM / TM) * (BN / TN))
gemm_kernel(const float* __restrict__ A, const float* __restrict__ B,
            const float* __restrict__ bias, float* __restrict__ C, int K, int relu) {
    constexpr int TCOLS   = BN / TN;
    constexpr int THREADS = (BM / TM) * (BN / TN);
    __shared__ float As[BK][BM];
    __shared__ float Bs[BK][BN];
    int tid = threadIdx.x;
    int tx = tid % TCOLS, ty = tid / TCOLS;
    size_t row0 = (size_t)blockIdx.x * BM;

    float acc[TM][TN];
    #pragma unroll
    for (int i = 0; i < TM; i++)
        #pragma unroll
        for (int j = 0; j < TN; j++) acc[i][j] = 0.0f;

    for (int k0 = 0; k0 < K; k0 += BK) {
        #pragma unroll
        for (int i = tid; i < BM * BK; i += THREADS) {
            int m = i / BK, kk = i % BK;
            As[kk][m] = A[(row0 + m) * K + k0 + kk];
        }
        #pragma unroll
        for (int i = tid; i < BK * BN; i += THREADS) {
            int kk = i / BN, n = i % BN;
            Bs[kk][n] = B[(size_t)(k0 + kk) * BN + n];
        }
        __syncthreads();
        #pragma unroll
        for (int kk = 0; kk < BK; kk++) {
            float a[TM], b[TN];
            #pragma unroll
            for (int i = 0; i < TM; i++) a[i] = As[kk][ty * TM + i];
            #pragma unroll
            for (int j = 0; j < TN; j++) b[j] = Bs[kk][tx * TN + j];
            #pragma unroll
            for (int i = 0; i < TM; i++)
                #pragma unroll
                for (int j = 0; j < TN; j++)
                    acc[i][j] = fmaf(a[i], b[j], acc[i][j]);
        }
        __syncthreads();
    }
    #pragma unroll
    for (int i = 0; i < TM; i++) {
        size_t r = row0 + ty * TM + i;
        #pragma unroll
        for (int j = 0; j < TN; j++) {
            int n = tx * TN + j;
            float v = acc[i][j];
            if (bias) v += bias[n];
            if (relu) v = fmaxf(v, 0.0f);
            C[r * BN + n] = v;
        }
    }
}

// ---------------- conv1d (k=3, pad=1) over row dim, per-graph boundaries ----------------
template <int BM, int BN, int BK, int TM, int TN>
__global__ void __launch_bounds__((BM / TM) * (BN / TN))
conv_kernel(const float* __restrict__ X, const float* __restrict__ W,
            const float* __restrict__ bias, float* __restrict__ C, int CIN) {
    constexpr int TCOLS   = BN / TN;
    constexpr int THREADS = (BM / TM) * (BN / TN);
    __shared__ float As[BK][BM + 2];
    __shared__ float Ws[3][BK][BN];
    int tid = threadIdx.x;
    int tx = tid % TCOLS, ty = tid / TCOLS;
    size_t row0 = (size_t)blockIdx.x * BM;
    int zlo = ((row0 % NPG) == 0);
    int zhi = (((row0 + BM) % NPG) == 0);

    float acc[TM][TN];
    #pragma unroll
    for (int i = 0; i < TM; i++)
        #pragma unroll
        for (int j = 0; j < TN; j++) acc[i][j] = 0.0f;

    for (int k0 = 0; k0 < CIN; k0 += BK) {
        #pragma unroll
        for (int i = tid; i < (BM + 2) * BK; i += THREADS) {
            int r = i / BK, kk = i % BK;
            float v = 0.0f;
            if (!((r == 0 && zlo) || (r == BM + 1 && zhi))) {
                size_t R = row0 - 1 + r;
                v = X[R * CIN + k0 + kk];
            }
            As[kk][r] = v;
        }
        #pragma unroll
        for (int i = tid; i < 3 * BK * BN; i += THREADS) {
            int s = i % 3;
            int t2 = i / 3;
            int n = t2 % BN, kk = t2 / BN;
            Ws[s][kk][n] = W[((size_t)n * CIN + k0 + kk) * 3 + s];
        }
        __syncthreads();
        #pragma unroll
        for (int kk = 0; kk < BK; kk++) {
            float a[TM + 2];
            #pragma unroll
            for (int i = 0; i < TM + 2; i++) a[i] = As[kk][ty * TM + i];
            float b0[TN], b1[TN], b2[TN];
            #pragma unroll
            for (int j = 0; j < TN; j++) {
                b0[j] = Ws[0][kk][tx * TN + j];
                b1[j] = Ws[1][kk][tx * TN + j];
                b2[j] = Ws[2][kk][tx * TN + j];
            }
            #pragma unroll
            for (int i = 0; i < TM; i++)
                #pragma unroll
                for (int j = 0; j < TN; j++) {
                    float v = acc[i][j];
                    v = fmaf(a[i],     b0[j], v);
                    v = fmaf(a[i + 1], b1[j], v);
                    v = fmaf(a[i + 2], b2[j], v);
                    acc[i][j] = v;
                }
        }
        __syncthreads();
    }
    #pragma unroll
    for (int i = 0; i < TM; i++) {
        size_t r = row0 + ty * TM + i;
        #pragma unroll
        for (int j = 0; j < TN; j++) {
            int n = tx * TN + j;
            float v = fmaxf(acc[i][j] + bias[n], 0.0f);
            C[r * BN + n] = v;
        }
    }
}

// ---------------- 3 scalar heads: sigmoid / softplus / sigmoid ----------------
__global__ void heads_kernel(const float* __restrict__ X,
                             const float* __restrict__ Wpi, const float* __restrict__ bpi,
                             const float* __restrict__ Wn,  const float* __restrict__ bn,
                             const float* __restrict__ Wp,  const float* __restrict__ bp,
                             float* __restrict__ out, int M) {
    int lane = threadIdx.x & 31;
    int warp = (blockIdx.x * blockDim.x + threadIdx.x) >> 5;
    int nw   = (gridDim.x * blockDim.x) >> 5;
    float4 wa = ((const float4*)Wpi)[lane];
    float4 wb = ((const float4*)Wn)[lane];
    float4 wc = ((const float4*)Wp)[lane];
    for (int r = warp; r < M; r += nw) {
        float4 x = ((const float4*)(X + (size_t)r * 128))[lane];
        float s1 = x.x * wa.x + x.y * wa.y + x.z * wa.z + x.w * wa.w;
        float s2 = x.x * wb.x + x.y * wb.y + x.z * wb.z + x.w * wb.w;
        float s3 = x.x * wc.x + x.y * wc.y + x.z * wc.z + x.w * wc.w;
        #pragma unroll
        for (int o = 16; o > 0; o >>= 1) {
            s1 += __shfl_xor_sync(0xffffffffu, s1, o);
            s2 += __shfl_xor_sync(0xffffffffu, s2, o);
            s3 += __shfl_xor_sync(0xffffffffu, s3, o);
        }
        if (lane == 0) {
            float zpi = s1 + bpi[0];
            float zn  = s2 + bn[0];
            float zp  = s3 + bp[0];
            out[r]         = 1.0f / (1.0f + expf(-zpi));
            out[M + r]     = (zn > 0.0f) ? (zn + log1pf(expf(-zn))) : log1pf(expf(zn));
            out[2 * M + r] = 1.0f / (1.0f + expf(-zp));
        }
    }
}

// ---------------- launch ----------------
extern "C" void kernel_launch(void* const* d_in, const int* in_sizes, int n_in,
                              void* d_out, int out_size) {
    const float* x     = (const float*)d_in[0];
    const void*  edges = d_in[1];
    const float* W1  = (const float*)d_in[3];  const float* b1  = (const float*)d_in[4];
    const float* W2  = (const float*)d_in[5];  const float* b2  = (const float*)d_in[6];
    const float* W3  = (const float*)d_in[7];  const float* b3  = (const float*)d_in[8];
    const float* tW1 = (const float*)d_in[9];  const float* tb1 = (const float*)d_in[10];
    const float* tW2 = (const float*)d_in[11]; const float* tb2 = (const float*)d_in[12];
    const float* tW3 = (const float*)d_in[13]; const float* tb3 = (const float*)d_in[14];
    const float* Wpi = (const float*)d_in[15]; const float* bpi = (const float*)d_in[16];
    const float* Wn  = (const float*)d_in[17]; const float* bn  = (const float*)d_in[18];
    const float* Wp  = (const float*)d_in[19]; const float* bp  = (const float*)d_in[20];
    float* out = (float*)d_out;

    const int TOT = in_sizes[0] / FDIM;   // 131072
    const int E   = in_sizes[1] / 2;      // 1048576

    float *dinv, *A1, *H1, *H2raw, *H2, *A3, *H3, *C1, *C2, *C3;
    int *cnt, *rowp, *curs, *adj;
    cudaGetSymbolAddress((void**)&dinv,  g_dinv);
    cudaGetSymbolAddress((void**)&cnt,   g_cnt);
    cudaGetSymbolAddress((void**)&rowp,  g_rowp);
    cudaGetSymbolAddress((void**)&curs,  g_curs);
    cudaGetSymbolAddress((void**)&adj,   g_adj);
    cudaGetSymbolAddress((void**)&A1,    g_A1);
    cudaGetSymbolAddress((void**)&H1,    g_H1);
    cudaGetSymbolAddress((void**)&H2raw, g_H2raw);
    cudaGetSymbolAddress((void**)&H2,    g_H2);
    cudaGetSymbolAddress((void**)&A3,    g_A3);
    cudaGetSymbolAddress((void**)&H3,    g_H3);
    cudaGetSymbolAddress((void**)&C1,    g_C1);
    cudaGetSymbolAddress((void**)&C2,    g_C2);
    cudaGetSymbolAddress((void**)&C3,    g_C3);

    const int gatherBlocks = (TOT * 32) / 256;   // warp per node

    detect_kernel<<<1, 32>>>((const unsigned int*)edges);

    // ---- CSR build (also provides degrees) ----
    zero_cnt_kernel<<<256, 256>>>(cnt, TOT);
    count_kernel<<<2048, 256>>>(edges, cnt, E);
    dinv_kernel<<<256, 256>>>(cnt, dinv, TOT);
    scan_kernel<<<1, 1024>>>(cnt, rowp, curs);
    fill_kernel<<<2048, 256>>>(edges, curs, adj, E);

    // ---- GCN layer 1: gather raw input (64-dim), then GEMM+bias+relu ----
    gather_kernel<64, 0><<<gatherBlocks, 256>>>(rowp, adj, dinv, x, nullptr, A1, TOT);
    gemm_kernel<128, 128, 8, 8, 8><<<TOT / 128, 256>>>(A1, W1, b1, H1, FDIM, 1);

    // ---- GCN layer 2: GEMM to 32, gather 32-dim, +bias, relu ----
    gemm_kernel<128, 32, 8, 8, 4><<<TOT / 128, 128>>>(H1, W2, nullptr, H2raw, HSD, 0);
    gather_kernel<32, 1><<<gatherBlocks, 256>>>(rowp, adj, dinv, H2raw, b2, H2, TOT);

    // ---- GCN layer 3: gather 32-dim input, then GEMM+bias+relu ----
    gather_kernel<32, 0><<<gatherBlocks, 256>>>(rowp, adj, dinv, H2, nullptr, A3, TOT);
    gemm_kernel<128, 128, 8, 8, 8><<<TOT / 128, 256>>>(A3, W3, b3, H3, RSD, 1);

    // ---- temporal conv stack (k=3, pad=1), relu each ----
    conv_kernel<128, 128, 8, 8, 8><<<TOT / 128, 256>>>(H3, tW1, tb1, C1, HSD);
    conv_kernel<128, 32, 8, 8, 4><<<TOT / 128, 128>>>(C1, tW2, tb2, C2, HSD);
    conv_kernel<128, 128, 8, 8, 8><<<TOT / 128, 256>>>(C2, tW3, tb3, C3, RSD);

    // ---- heads ----
    heads_kernel<<<TOT / 8, 256>>>(C3, Wpi, bpi, Wn, bn, Wp, bp, out, TOT);
}

// round 3
// speedup vs baseline: 1.1378x; 1.1378x over previous
#include <cuda_runtime.h>
#include <math.h>

// ---------------- problem constants ----------------
#define TOTN   131072      // B*N nodes
#define EMAX   1048576
#define FDIM   64
#define HSD    128
#define RSD    32
#define NPG    4096        // nodes per graph (temporal length)

// ---------------- packed f32x2 helpers (sm_103a FFMA2 path) ----------------
typedef unsigned long long u64t;

__device__ __forceinline__ u64t pk2(float lo, float hi) {
    u64t r;
    asm("mov.b64 %0, {%1, %2};" : "=l"(r) : "f"(lo), "f"(hi));
    return r;
}
__device__ __forceinline__ u64t fma2(u64t a, u64t b, u64t c) {
    u64t d;
    asm("fma.rn.f32x2 %0, %1, %2, %3;" : "=l"(d) : "l"(a), "l"(b), "l"(c));
    return d;
}
__device__ __forceinline__ float2 upk2(u64t v) {
    float2 f;
    asm("mov.b64 {%0, %1}, %2;" : "=f"(f.x), "=f"(f.y) : "l"(v));
    return f;
}

// ---------------- device scratch (no cudaMalloc allowed) ----------------
__device__ int   g_is64;
__device__ float g_dinv [TOTN];
__device__ int   g_cnt  [TOTN];
__device__ int   g_rowp [TOTN + 1];
__device__ int   g_curs [TOTN];
__device__ int   g_adj  [EMAX];
__device__ float g_A1   [TOTN * FDIM];
__device__ float g_H1   [TOTN * HSD];
__device__ float g_H2raw[TOTN * RSD];
__device__ float g_H2   [TOTN * RSD];
__device__ float g_A3   [TOTN * RSD];
__device__ float g_H3   [TOTN * HSD];
__device__ float g_C1   [TOTN * HSD];
__device__ float g_C2   [TOTN * RSD];
__device__ float g_C3   [TOTN * HSD];

// ---------------- edge dtype detection ----------------
__global__ void detect_kernel(const unsigned int* e) {
    if (blockIdx.x == 0 && threadIdx.x == 0) {
        int ok = 1;
        #pragma unroll 1
        for (int i = 0; i < 64; i++)
            if (e[2 * i + 1] != 0u) { ok = 0; break; }
        g_is64 = ok;
    }
}

__device__ __forceinline__ int edge_at(const void* e, int idx, int is64) {
    if (is64) return (int)((const long long*)e)[idx];
    return ((const int*)e)[idx];
}

// ---------------- CSR build ----------------
__global__ void zero_cnt_kernel(int* cnt, int n) {
    int i  = blockIdx.x * blockDim.x + threadIdx.x;
    int st = gridDim.x * blockDim.x;
    for (; i < n; i += st) cnt[i] = 0;
}

__global__ void count_kernel(const void* edges, int* cnt, int E) {
    int is64 = g_is64;
    int i  = blockIdx.x * blockDim.x + threadIdx.x;
    int st = gridDim.x * blockDim.x;
    for (; i < E; i += st) {
        int d = edge_at(edges, E + i, is64);
        atomicAdd(&cnt[d], 1);
    }
}

__global__ void dinv_kernel(const int* __restrict__ cnt, float* dinv, int n) {
    int i  = blockIdx.x * blockDim.x + threadIdx.x;
    int st = gridDim.x * blockDim.x;
    for (; i < n; i += st) dinv[i] = rsqrtf((float)cnt[i] + 1.0f);
}

__global__ void __launch_bounds__(1024)
scan_kernel(const int* __restrict__ cnt, int* row_ptr, int* cursor) {
    const int T = 1024;
    const int C = TOTN / T;
    int tid  = threadIdx.x;
    int base = tid * C;
    int s = 0;
    #pragma unroll 8
    for (int c = 0; c < C; c++) s += cnt[base + c];
    __shared__ int sh[T];
    sh[tid] = s;
    __syncthreads();
    for (int off = 1; off < T; off <<= 1) {
        int v = (tid >= off) ? sh[tid - off] : 0;
        __syncthreads();
        sh[tid] += v;
        __syncthreads();
    }
    int run = sh[tid] - s;
    #pragma unroll 8
    for (int c = 0; c < C; c++) {
        row_ptr[base + c] = run;
        cursor[base + c]  = run;
        run += cnt[base + c];
    }
    if (tid == T - 1) row_ptr[TOTN] = run;
}

__global__ void fill_kernel(const void* edges, int* cursor, int* adj, int E) {
    int is64 = g_is64;
    int i  = blockIdx.x * blockDim.x + threadIdx.x;
    int st = gridDim.x * blockDim.x;
    for (; i < E; i += st) {
        int s = edge_at(edges, i, is64);
        int d = edge_at(edges, E + i, is64);
        int pos = atomicAdd(&cursor[d], 1);
        adj[pos] = s;
    }
}

// ---------------- CSR gather + fused epilogue ----------------
// OUT[d] = di^2 * ( sum_{s in N(d)} dinv[s]*X[s]  +  X[d] )   (+bias, relu)
template <int D, int BIASRELU>
__global__ void gather_kernel(const int* __restrict__ row_ptr, const int* __restrict__ adj,
                              const float* __restrict__ dinv, const float* __restrict__ X,
                              const float* __restrict__ bias, float* __restrict__ OUT, int n) {
    int lane = threadIdx.x & 31;
    int node = (blockIdx.x * blockDim.x + threadIdx.x) >> 5;
    if (node >= n) return;
    int beg = row_ptr[node];
    int end = row_ptr[node + 1];
    float di = dinv[node];
    float c  = di * di;
    if (D == 64) {
        float ax = 0.0f, ay = 0.0f;
        for (int j = beg; j < end; j++) {
            int s = adj[j];
            float ws = __ldg(&dinv[s]);
            float2 v = ((const float2*)(X + (size_t)s * 64))[lane];
            ax = fmaf(ws, v.x, ax);
            ay = fmaf(ws, v.y, ay);
        }
        float2 xv = ((const float2*)(X + (size_t)node * 64))[lane];
        float2 o;
        o.x = c * (ax + xv.x);
        o.y = c * (ay + xv.y);
        if (BIASRELU) {
            o.x = fmaxf(o.x + bias[2 * lane],     0.0f);
            o.y = fmaxf(o.y + bias[2 * lane + 1], 0.0f);
        }
        ((float2*)(OUT + (size_t)node * 64))[lane] = o;
    } else {
        float acc = 0.0f;
        for (int j = beg; j < end; j++) {
            int s = adj[j];
            float ws = __ldg(&dinv[s]);
            acc = fmaf(ws, X[(size_t)s * 32 + lane], acc);
        }
        float v = c * (acc + X[(size_t)node * 32 + lane]);
        if (BIASRELU) v = fmaxf(v + bias[lane], 0.0f);
        OUT[(size_t)node * 32 + lane] = v;
    }
}

// ---------------- tiled GEMM with packed f32x2 FMA ----------------
// C[M,BN] = A[M,K] @ B[K,BN] (+bias)(+relu), TN even
template <int BM, int BN, int BK, int TM, int TN>
__global__ void __launch_bounds__((BM / TM) * (BN / TN))
gemm_kernel(const float* __restrict__ A, const float* __restrict__ B,
            const float* __restrict__ bias, float* __restrict__ C, int K, int relu) {
    constexpr int TCOLS   = BN / TN;
    constexpr int THREADS = (BM / TM) * (BN / TN);
    constexpr int TN2     = TN / 2;
    __shared__ __align__(16) float As[BK][BM];
    __shared__ __align__(16) float Bs[BK][BN];
    int tid = threadIdx.x;
    int tx = tid % TCOLS, ty = tid / TCOLS;
    size_t row0 = (size_t)blockIdx.x * BM;

    u64t acc[TM][TN2];
    const u64t z = 0ull;
    #pragma unroll
    for (int i = 0; i < TM; i++)
        #pragma unroll
        for (int j = 0; j < TN2; j++) acc[i][j] = z;

    for (int k0 = 0; k0 < K; k0 += BK) {
        #pragma unroll
        for (int i = tid; i < BM * BK; i += THREADS) {
            int m = i / BK, kk = i % BK;
            As[kk][m] = A[(row0 + m) * K + k0 + kk];
        }
        #pragma unroll
        for (int i = tid; i < BK * BN; i += THREADS) {
            int kk = i / BN, n = i % BN;
            Bs[kk][n] = B[(size_t)(k0 + kk) * BN + n];
        }
        __syncthreads();
        #pragma unroll
        for (int kk = 0; kk < BK; kk++) {
            u64t a2[TM], b2[TN2];
            #pragma unroll
            for (int i = 0; i < TM; i++) {
                float a = As[kk][ty * TM + i];
                a2[i] = pk2(a, a);
            }
            const u64t* brow = (const u64t*)&Bs[kk][tx * TN];
            #pragma unroll
            for (int j = 0; j < TN2; j++) b2[j] = brow[j];
            #pragma unroll
            for (int i = 0; i < TM; i++)
                #pragma unroll
                for (int j = 0; j < TN2; j++)
                    acc[i][j] = fma2(a2[i], b2[j], acc[i][j]);
        }
        __syncthreads();
    }
    #pragma unroll
    for (int i = 0; i < TM; i++) {
        size_t r = row0 + ty * TM + i;
        #pragma unroll
        for (int j = 0; j < TN2; j++) {
            int n = tx * TN + 2 * j;
            float2 v = upk2(acc[i][j]);
            if (bias) { v.x += bias[n]; v.y += bias[n + 1]; }
            if (relu) { v.x = fmaxf(v.x, 0.0f); v.y = fmaxf(v.y, 0.0f); }
            *(float2*)&C[r * BN + n] = v;
        }
    }
}

// ---------------- conv1d (k=3, pad=1) with packed f32x2 FMA ----------------
template <int BM, int BN, int BK, int TM, int TN>
__global__ void __launch_bounds__((BM / TM) * (BN / TN))
conv_kernel(const float* __restrict__ X, const float* __restrict__ W,
            const float* __restrict__ bias, float* __restrict__ C, int CIN) {
    constexpr int TCOLS   = BN / TN;
    constexpr int THREADS = (BM / TM) * (BN / TN);
    constexpr int TN2     = TN / 2;
    __shared__ __align__(16) float As[BK][BM + 2];
    __shared__ __align__(16) float Ws[3][BK][BN];
    int tid = threadIdx.x;
    int tx = tid % TCOLS, ty = tid / TCOLS;
    size_t row0 = (size_t)blockIdx.x * BM;
    int zlo = ((row0 % NPG) == 0);
    int zhi = (((row0 + BM) % NPG) == 0);

    u64t acc[TM][TN2];
    #pragma unroll
    for (int i = 0; i < TM; i++)
        #pragma unroll
        for (int j = 0; j < TN2; j++) acc[i][j] = 0ull;

    for (int k0 = 0; k0 < CIN; k0 += BK) {
        #pragma unroll
        for (int i = tid; i < (BM + 2) * BK; i += THREADS) {
            int r = i / BK, kk = i % BK;
            float v = 0.0f;
            if (!((r == 0 && zlo) || (r == BM + 1 && zhi))) {
                size_t R = row0 - 1 + r;
                v = X[R * CIN + k0 + kk];
            }
            As[kk][r] = v;
        }
        #pragma unroll
        for (int i = tid; i < 3 * BK * BN; i += THREADS) {
            int s = i % 3;
            int t2 = i / 3;
            int n = t2 % BN, kk = t2 / BN;
            Ws[s][kk][n] = W[((size_t)n * CIN + k0 + kk) * 3 + s];
        }
        __syncthreads();
        #pragma unroll
        for (int kk = 0; kk < BK; kk++) {
            float a[TM + 2];
            #pragma unroll
            for (int i = 0; i < TM + 2; i++) a[i] = As[kk][ty * TM + i];
            u64t a2[TM + 2];
            #pragma unroll
            for (int i = 0; i < TM + 2; i++) a2[i] = pk2(a[i], a[i]);
            const u64t* b0 = (const u64t*)&Ws[0][kk][tx * TN];
            const u64t* b1 = (const u64t*)&Ws[1][kk][tx * TN];
            const u64t* b2 = (const u64t*)&Ws[2][kk][tx * TN];
            u64t w0[TN2], w1[TN2], w2[TN2];
            #pragma unroll
            for (int j = 0; j < TN2; j++) { w0[j] = b0[j]; w1[j] = b1[j]; w2[j] = b2[j]; }
            #pragma unroll
            for (int i = 0; i < TM; i++)
                #pragma unroll
                for (int j = 0; j < TN2; j++) {
                    u64t v = acc[i][j];
                    v = fma2(a2[i],     w0[j], v);
                    v = fma2(a2[i + 1], w1[j], v);
                    v = fma2(a2[i + 2], w2[j], v);
                    acc[i][j] = v;
                }
        }
        __syncthreads();
    }
    #pragma unroll
    for (int i = 0; i < TM; i++) {
        size_t r = row0 + ty * TM + i;
        #pragma unroll
        for (int j = 0; j < TN2; j++) {
            int n = tx * TN + 2 * j;
            float2 v = upk2(acc[i][j]);
            v.x = fmaxf(v.x + bias[n],     0.0f);
            v.y = fmaxf(v.y + bias[n + 1], 0.0f);
            *(float2*)&C[r * BN + n] = v;
        }
    }
}

// ---------------- 3 scalar heads ----------------
__global__ void heads_kernel(const float* __restrict__ X,
                             const float* __restrict__ Wpi, const float* __restrict__ bpi,
                             const float* __restrict__ Wn,  const float* __restrict__ bn,
                             const float* __restrict__ Wp,  const float* __restrict__ bp,
                             float* __restrict__ out, int M) {
    int lane = threadIdx.x & 31;
    int warp = (blockIdx.x * blockDim.x + threadIdx.x) >> 5;
    int nw   = (gridDim.x * blockDim.x) >> 5;
    float4 wa = ((const float4*)Wpi)[lane];
    float4 wb = ((const float4*)Wn)[lane];
    float4 wc = ((const float4*)Wp)[lane];
    for (int r = warp; r < M; r += nw) {
        float4 x = ((const float4*)(X + (size_t)r * 128))[lane];
        float s1 = x.x * wa.x + x.y * wa.y + x.z * wa.z + x.w * wa.w;
        float s2 = x.x * wb.x + x.y * wb.y + x.z * wb.z + x.w * wb.w;
        float s3 = x.x * wc.x + x.y * wc.y + x.z * wc.z + x.w * wc.w;
        #pragma unroll
        for (int o = 16; o > 0; o >>= 1) {
            s1 += __shfl_xor_sync(0xffffffffu, s1, o);
            s2 += __shfl_xor_sync(0xffffffffu, s2, o);
            s3 += __shfl_xor_sync(0xffffffffu, s3, o);
        }
        if (lane == 0) {
            float zpi = s1 + bpi[0];
            float zn  = s2 + bn[0];
            float zp  = s3 + bp[0];
            out[r]         = 1.0f / (1.0f + expf(-zpi));
            out[M + r]     = (zn > 0.0f) ? (zn + log1pf(expf(-zn))) : log1pf(expf(zn));
            out[2 * M + r] = 1.0f / (1.0f + expf(-zp));
        }
    }
}

// ---------------- launch ----------------
extern "C" void kernel_launch(void* const* d_in, const int* in_sizes, int n_in,
                              void* d_out, int out_size) {
    const float* x     = (const float*)d_in[0];
    const void*  edges = d_in[1];
    const float* W1  = (const float*)d_in[3];  const float* b1  = (const float*)d_in[4];
    const float* W2  = (const float*)d_in[5];  const float* b2  = (const float*)d_in[6];
    const float* W3  = (const float*)d_in[7];  const float* b3  = (const float*)d_in[8];
    const float* tW1 = (const float*)d_in[9];  const float* tb1 = (const float*)d_in[10];
    const float* tW2 = (const float*)d_in[11]; const float* tb2 = (const float*)d_in[12];
    const float* tW3 = (const float*)d_in[13]; const float* tb3 = (const float*)d_in[14];
    const float* Wpi = (const float*)d_in[15]; const float* bpi = (const float*)d_in[16];
    const float* Wn  = (const float*)d_in[17]; const float* bn  = (const float*)d_in[18];
    const float* Wp  = (const float*)d_in[19]; const float* bp  = (const float*)d_in[20];
    float* out = (float*)d_out;

    const int TOT = in_sizes[0] / FDIM;
    const int E   = in_sizes[1] / 2;

    float *dinv, *A1, *H1, *H2raw, *H2, *A3, *H3, *C1, *C2, *C3;
    int *cnt, *rowp, *curs, *adj;
    cudaGetSymbolAddress((void**)&dinv,  g_dinv);
    cudaGetSymbolAddress((void**)&cnt,   g_cnt);
    cudaGetSymbolAddress((void**)&rowp,  g_rowp);
    cudaGetSymbolAddress((void**)&curs,  g_curs);
    cudaGetSymbolAddress((void**)&adj,   g_adj);
    cudaGetSymbolAddress((void**)&A1,    g_A1);
    cudaGetSymbolAddress((void**)&H1,    g_H1);
    cudaGetSymbolAddress((void**)&H2raw, g_H2raw);
    cudaGetSymbolAddress((void**)&H2,    g_H2);
    cudaGetSymbolAddress((void**)&A3,    g_A3);
    cudaGetSymbolAddress((void**)&H3,    g_H3);
    cudaGetSymbolAddress((void**)&C1,    g_C1);
    cudaGetSymbolAddress((void**)&C2,    g_C2);
    cudaGetSymbolAddress((void**)&C3,    g_C3);

    const int gatherBlocks = (TOT * 32) / 256;

    detect_kernel<<<1, 32>>>((const unsigned int*)edges);

    // ---- CSR build ----
    zero_cnt_kernel<<<256, 256>>>(cnt, TOT);
    count_kernel<<<2048, 256>>>(edges, cnt, E);
    dinv_kernel<<<256, 256>>>(cnt, dinv, TOT);
    scan_kernel<<<1, 1024>>>(cnt, rowp, curs);
    fill_kernel<<<2048, 256>>>(edges, curs, adj, E);

    // ---- GCN layer 1 ----
    gather_kernel<64, 0><<<gatherBlocks, 256>>>(rowp, adj, dinv, x, nullptr, A1, TOT);
    gemm_kernel<128, 128, 8, 8, 8><<<TOT / 128, 256>>>(A1, W1, b1, H1, FDIM, 1);

    // ---- GCN layer 2 ----
    gemm_kernel<128, 32, 8, 8, 4><<<TOT / 128, 128>>>(H1, W2, nullptr, H2raw, HSD, 0);
    gather_kernel<32, 1><<<gatherBlocks, 256>>>(rowp, adj, dinv, H2raw, b2, H2, TOT);

    // ---- GCN layer 3 ----
    gather_kernel<32, 0><<<gatherBlocks, 256>>>(rowp, adj, dinv, H2, nullptr, A3, TOT);
    gemm_kernel<128, 128, 8, 8, 8><<<TOT / 128, 256>>>(A3, W3, b3, H3, RSD, 1);

    // ---- temporal conv stack ----
    conv_kernel<128, 128, 8, 8, 8><<<TOT / 128, 256>>>(H3, tW1, tb1, C1, HSD);
    conv_kernel<128, 32, 8, 8, 4><<<TOT / 128, 128>>>(C1, tW2, tb2, C2, HSD);
    conv_kernel<128, 128, 8, 8, 8><<<TOT / 128, 256>>>(C2, tW3, tb3, C3, RSD);

    // ---- heads ----
    heads_kernel<<<TOT / 8, 256>>>(C3, Wpi, bpi, Wn, bn, Wp, bp, out, TOT);
}